// round 6
// baseline (speedup 1.0000x reference)
#include <cuda_runtime.h>
#include <cuda_bf16.h>

typedef unsigned long long u64;

// Problem constants
#define B_   16
#define K_   256
#define T_   64
#define D_   128
// e = C_LIN*(P+Q) + C_ABS*sum_d a_d*|u+vb| + bias   (alpha = 0.2)
#define C_LIN 0.6f
#define C_ABS 0.4f
#define ABSMASK2 0x7FFFFFFF7FFFFFFFULL

__device__ __forceinline__ u64 addx2(u64 a, u64 b) {
    u64 r; asm("add.rn.f32x2 %0,%1,%2;" : "=l"(r) : "l"(a), "l"(b)); return r;
}
__device__ __forceinline__ u64 fmax2p(u64 a, u64 b, u64 c) {
    u64 r; asm("fma.rn.f32x2 %0,%1,%2,%3;" : "=l"(r) : "l"(a), "l"(b), "l"(c)); return r;
}
__device__ __forceinline__ u64 dup2(float v) {
    u64 r; asm("mov.b64 %0, {%1, %1};" : "=l"(r) : "f"(v)); return r;
}
__device__ __forceinline__ float lo32(u64 v) { return __uint_as_float((unsigned)v); }
__device__ __forceinline__ float hi32(u64 v) { return __uint_as_float((unsigned)(v >> 32)); }

// Scratch (device globals: allocation-free rule)
__device__ float g_U [B_*K_*D_];   // u[b,k,d]
__device__ float g_Vb[B_*K_*D_];   // v[b,k,d] + b_lin[d]

// ---------------------------------------------------------------------------
// Kernel A: register-tiled GEMM with packed f32x2 FMAs (unchanged).
// ---------------------------------------------------------------------------
#define PADA 68
#define KA_SMEM_FLOATS (256*PADA + 32*PADA)   // 78336 B

__global__ void __launch_bounds__(256)
kA(const float* __restrict__ x, const float* __restrict__ W,
   const float* __restrict__ b_lin)
{
    extern __shared__ float sm[];
    float* Ws = sm;               // 256 x 68
    float* xs = sm + 256*PADA;    // 32 x 68

    const int tid  = threadIdx.x;
    const int row0 = blockIdx.x * 32;

    for (int idx = tid; idx < 256*64; idx += 256) {
        const int n = idx >> 6, t = idx & 63;
        Ws[n*PADA + t] = (n < 128) ? W[n*128 + t] : W[(n-128)*128 + 64 + t];
    }
    for (int idx = tid; idx < 32*64; idx += 256) {
        const int r = idx >> 6, t = idx & 63;
        xs[r*PADA + t] = x[(row0 + r)*T_ + t];
    }
    __syncthreads();

    const int l = tid & 31;
    const int w = tid >> 5;

    u64 acc2[4][8];
    #pragma unroll
    for (int r = 0; r < 4; r++)
        #pragma unroll
        for (int nn = 0; nn < 8; nn++) acc2[r][nn] = 0ull;

    #pragma unroll 4
    for (int k4 = 0; k4 < 16; k4++) {
        ulonglong2 xv[4], wv[8];
        #pragma unroll
        for (int r = 0; r < 4; r++)
            xv[r] = *(const ulonglong2*)(xs + (4*w + r)*PADA + 4*k4);
        #pragma unroll
        for (int nn = 0; nn < 8; nn++)
            wv[nn] = *(const ulonglong2*)(Ws + (l + 32*nn)*PADA + 4*k4);
        #pragma unroll
        for (int r = 0; r < 4; r++)
            #pragma unroll
            for (int nn = 0; nn < 8; nn++) {
                acc2[r][nn] = fmax2p(xv[r].x, wv[nn].x, acc2[r][nn]);
                acc2[r][nn] = fmax2p(xv[r].y, wv[nn].y, acc2[r][nn]);
            }
    }

    float bl[4];
    #pragma unroll
    for (int nn = 0; nn < 4; nn++) bl[nn] = __ldg(b_lin + l + 32*nn);

    #pragma unroll
    for (int r = 0; r < 4; r++) {
        const int row = row0 + 4*w + r;
        #pragma unroll
        for (int nn = 0; nn < 4; nn++)
            g_U[row*D_ + l + 32*nn] = lo32(acc2[r][nn]) + hi32(acc2[r][nn]);
        #pragma unroll
        for (int nn = 0; nn < 4; nn++)
            g_Vb[row*D_ + l + 32*nn] = lo32(acc2[r][nn+4]) + hi32(acc2[r][nn+4]) + bl[nn];
    }
}

// ---------------------------------------------------------------------------
// Kernel B: transposed layout, 1024 threads = 32 warps (occ 50%).
// Grid (8 i-groups x 16 b) = 128 blocks. Warp w owns j in [8w, 8w+8);
// lanes = the block's 32 i rows. Per dc: 1 lane-varying u LDS.128 +
// 8 broadcast v loads + 1 broadcast a. Softmax combines 32 warp-partials.
// Epilogue: warp w = i-row w, lanes = t-pairs.
// ---------------------------------------------------------------------------
#define VBS_F   (K_*132)                   // 33792
#define US_OFF  (VBS_F)                    // + 32*132 = 4224
#define AS_OFF  (US_OFF + 32*132)          // 38016
#define QS_OFF  (AS_OFF + 128)             // 38144
#define PS_OFF  (QS_OFF + 256)             // 38400
#define MR_OFF  (PS_OFF + 32)              // 38432  (32*32)
#define SR_OFF  (MR_OFF + 1024)            // 39456  (32*32)
#define WS_OFF  (SR_OFF + 1024)            // 40480
#define KB_SMEM_FLOATS (WS_OFF + K_*34)    // 49184 floats = 196736 B

__global__ void __launch_bounds__(1024)
kB(const float* __restrict__ x, const float* __restrict__ a,
   const float* __restrict__ bias, float* __restrict__ out)
{
    extern __shared__ float sm[];
    float* Vbs  = sm;
    float* Us   = sm + US_OFF;
    float* as_  = sm + AS_OFF;
    float* Qs   = sm + QS_OFF;
    float* Ps   = sm + PS_OFF;
    float* mred = sm + MR_OFF;
    float* sred = sm + SR_OFF;
    float* ws   = sm + WS_OFF;   // ws[j*34 + il]

    const int tid = threadIdx.x;
    const int b   = blockIdx.y;
    const int igbase = blockIdx.x * 32;

    // ---- stage Vb[b] (pad 33 float4/row), 32 U rows, a ----
    {
        const float4* vg4  = (const float4*)g_Vb + b * (K_*D_/4);
        float4*       vbs4 = (float4*)Vbs;
        for (int idx = tid; idx < K_*D_/4; idx += 1024) {
            const int j = idx >> 5, c = idx & 31;
            vbs4[j*33 + c] = vg4[idx];
        }
        const float4* ug4 = (const float4*)g_U + (b*K_ + igbase) * (D_/4);
        float4*       us4 = (float4*)Us;
        for (int idx = tid; idx < 32*D_/4; idx += 1024) {
            const int il = idx >> 5, c = idx & 31;
            us4[il*33 + c] = ug4[idx];
        }
        if (tid < 128) as_[tid] = a[tid];
    }
    __syncthreads();

    // ---- P/Q prologue: Q[j] = sum_d a_d*vb,  P[il] = sum_d a_d*u ----
    if (tid < 256) {
        const float4* a4 = (const float4*)as_;
        const float4* v4 = (const float4*)Vbs + tid*33;
        float q = 0.f;
        #pragma unroll 8
        for (int dc = 0; dc < 32; dc++) {
            const float4 av = a4[dc], vv = v4[dc];
            q += av.x*vv.x + av.y*vv.y + av.z*vv.z + av.w*vv.w;
        }
        Qs[tid] = q;
    } else if (tid < 288) {
        const int il = tid - 256;
        const float4* a4 = (const float4*)as_;
        const float4* u4 = (const float4*)Us + il*33;
        float p = 0.f;
        #pragma unroll 8
        for (int dc = 0; dc < 32; dc++) {
            const float4 av = a4[dc], uv = u4[dc];
            p += av.x*uv.x + av.y*uv.y + av.z*uv.z + av.w*uv.w;
        }
        Ps[il] = p;
    }
    __syncthreads();

    const int w  = tid >> 5;
    const int l  = tid & 31;           // lane = local i row
    const int j0 = w * 8;              // warp's j chunk (8 rows)

    // ---- e-loop: acc[jj] = packed sum_d a_d * |u_{l,d} + vb_{j0+jj,d}| ----
    u64 acc[8];
    #pragma unroll
    for (int jj = 0; jj < 8; jj++) acc[jj] = 0ull;

    {
        const ulonglong2* vbs2 = (const ulonglong2*)Vbs;   // row stride 33 (u64x2)
        const ulonglong2* us2  = (const ulonglong2*)Us;
        const ulonglong2* a2   = (const ulonglong2*)as_;
        for (int dc = 0; dc < 32; dc++) {
            const ulonglong2 uv = us2[l*33 + dc];          // lane-varying, conflict-free
            const ulonglong2 av = a2[dc];                  // broadcast
            #pragma unroll
            for (int jj = 0; jj < 8; jj++) {
                const ulonglong2 vv = vbs2[(j0 + jj)*33 + dc];  // broadcast
                u64 z;
                z = addx2(uv.x, vv.x); acc[jj] = fmax2p(av.x, z & ABSMASK2, acc[jj]);
                z = addx2(uv.y, vv.y); acc[jj] = fmax2p(av.y, z & ABSMASK2, acc[jj]);
            }
        }
    }

    // ---- finish e for (i=l, j=j0..j0+8), cross-warp softmax ----
    float e[8];
    {
        const float P  = Ps[l];
        const int   ig = igbase + l;
        const float4* brow4 = (const float4*)(bias + ig*K_ + j0);
        float m = -1e30f;
        #pragma unroll
        for (int q4 = 0; q4 < 2; q4++) {
            const float4 bv = brow4[q4];
            const float bb[4] = {bv.x, bv.y, bv.z, bv.w};
            #pragma unroll
            for (int r = 0; r < 4; r++) {
                const int jj = q4*4 + r;
                const float A  = lo32(acc[jj]) + hi32(acc[jj]);
                const float ev = fmaf(C_LIN, P + Qs[j0 + jj], fmaf(C_ABS, A, bb[r]));
                e[jj] = ev;
                m = fmaxf(m, ev);
            }
        }
        mred[w*32 + l] = m;
    }
    __syncthreads();
    {
        float M = mred[l];
        #pragma unroll
        for (int wp = 1; wp < 32; wp++) M = fmaxf(M, mred[wp*32 + l]);
        float s = 0.f;
        #pragma unroll
        for (int jj = 0; jj < 8; jj++) { e[jj] = __expf(e[jj] - M); s += e[jj]; }
        sred[w*32 + l] = s;
    }
    __syncthreads();
    {
        float S = sred[l];
        #pragma unroll
        for (int wp = 1; wp < 32; wp++) S += sred[wp*32 + l];
        const float inv = __fdividef(1.f, S);
        #pragma unroll
        for (int jj = 0; jj < 8; jj++)
            ws[(j0 + jj)*34 + l] = e[jj] * inv;     // lanes -> distinct banks
    }
    __syncthreads();

    // ---- overlay x[b] onto the (now dead) Vb smem region ----
    {
        float4*       xs4 = (float4*)sm;
        const float4* xg4 = (const float4*)x + b * (K_*T_/4);
        for (int idx = tid; idx < K_*T_/4; idx += 1024) xs4[idx] = xg4[idx];
    }
    __syncthreads();

    // ---- epilogue (packed): warp w -> i row w, lanes = t-pairs ----
    {
        const u64* xs2 = (const u64*)sm;     // x[j][t] as t-pairs
        u64 h0 = 0ull;
        #pragma unroll 8
        for (int j = 0; j < K_; j++) {
            const float wv = ws[j*34 + w];            // broadcast
            const u64  xv = xs2[j*32 + l];
            h0 = fmax2p(dup2(wv), xv, h0);
        }
        const int row0 = (b*K_ + igbase + w)*T_ + 2*l;
        float2 o0;
        o0.x = __fdividef(1.f, 1.f + __expf(-lo32(h0)));
        o0.y = __fdividef(1.f, 1.f + __expf(-hi32(h0)));
        *(float2*)(out + row0) = o0;
    }
}

// ---------------------------------------------------------------------------
extern "C" void kernel_launch(void* const* d_in, const int* in_sizes, int n_in,
                              void* d_out, int out_size)
{
    const float* x     = (const float*)d_in[0];
    // d_in[1] = embedding (unused by the reference computation)
    const float* W     = (const float*)d_in[2];
    const float* b_lin = (const float*)d_in[3];
    const float* a     = (const float*)d_in[4];
    const float* bias  = (const float*)d_in[5];
    float* out = (float*)d_out;

    const int smemA = KA_SMEM_FLOATS * 4;   // 78336 B
    const int smemB = KB_SMEM_FLOATS * 4;   // 196736 B
    cudaFuncSetAttribute(kA, cudaFuncAttributeMaxDynamicSharedMemorySize, smemA);
    cudaFuncSetAttribute(kB, cudaFuncAttributeMaxDynamicSharedMemorySize, smemB);

    kA<<<128, 256, smemA>>>(x, W, b_lin);
    kB<<<dim3(8, 16), 1024, smemB>>>(x, a, bias, out);
}

// round 7
// speedup vs baseline: 1.1912x; 1.1912x over previous
#include <cuda_runtime.h>
#include <cuda_bf16.h>

typedef unsigned long long u64;

// Problem constants
#define B_   16
#define K_   256
#define T_   64
#define D_   128
// e = C_LIN*(P+Q) + C_ABS*sum_d a_d*|u+vb| + bias   (alpha = 0.2)
#define C_LIN 0.6f
#define C_ABS 0.4f
#define ABSMASK2 0x7FFFFFFF7FFFFFFFULL

__device__ __forceinline__ u64 addx2(u64 a, u64 b) {
    u64 r; asm("add.rn.f32x2 %0,%1,%2;" : "=l"(r) : "l"(a), "l"(b)); return r;
}
__device__ __forceinline__ u64 fmax2p(u64 a, u64 b, u64 c) {
    u64 r; asm("fma.rn.f32x2 %0,%1,%2,%3;" : "=l"(r) : "l"(a), "l"(b), "l"(c)); return r;
}
__device__ __forceinline__ u64 dup2(float v) {
    u64 r; asm("mov.b64 %0, {%1, %1};" : "=l"(r) : "f"(v)); return r;
}
__device__ __forceinline__ float lo32(u64 v) { return __uint_as_float((unsigned)v); }
__device__ __forceinline__ float hi32(u64 v) { return __uint_as_float((unsigned)(v >> 32)); }

// Scratch (device globals: allocation-free rule)
__device__ float g_U [B_*K_*D_];   // u[b,k,d]
__device__ float g_Vb[B_*K_*D_];   // v[b,k,d] + b_lin[d]
__device__ float g_P [B_*K_];      // sum_d a_d * u
__device__ float g_Q [B_*K_];      // sum_d a_d * vb

// ---------------------------------------------------------------------------
// Kernel A: register-tiled GEMM (f32x2) + in-register P/Q reductions.
// ---------------------------------------------------------------------------
#define PADA 68
#define KA_SMEM_FLOATS (256*PADA + 32*PADA + 128)   // + a[] stage

__global__ void __launch_bounds__(256)
kA(const float* __restrict__ x, const float* __restrict__ W,
   const float* __restrict__ b_lin, const float* __restrict__ a)
{
    extern __shared__ float sm[];
    float* Ws  = sm;               // 256 x 68
    float* xs  = sm + 256*PADA;    // 32 x 68
    float* asA = xs + 32*PADA;     // 128

    const int tid  = threadIdx.x;
    const int row0 = blockIdx.x * 32;

    for (int idx = tid; idx < 256*64; idx += 256) {
        const int n = idx >> 6, t = idx & 63;
        Ws[n*PADA + t] = (n < 128) ? W[n*128 + t] : W[(n-128)*128 + 64 + t];
    }
    for (int idx = tid; idx < 32*64; idx += 256) {
        const int r = idx >> 6, t = idx & 63;
        xs[r*PADA + t] = x[(row0 + r)*T_ + t];
    }
    if (tid < 128) asA[tid] = a[tid];
    __syncthreads();

    const int l = tid & 31;
    const int w = tid >> 5;

    u64 acc2[4][8];
    #pragma unroll
    for (int r = 0; r < 4; r++)
        #pragma unroll
        for (int nn = 0; nn < 8; nn++) acc2[r][nn] = 0ull;

    #pragma unroll 4
    for (int k4 = 0; k4 < 16; k4++) {
        ulonglong2 xv[4], wv[8];
        #pragma unroll
        for (int r = 0; r < 4; r++)
            xv[r] = *(const ulonglong2*)(xs + (4*w + r)*PADA + 4*k4);
        #pragma unroll
        for (int nn = 0; nn < 8; nn++)
            wv[nn] = *(const ulonglong2*)(Ws + (l + 32*nn)*PADA + 4*k4);
        #pragma unroll
        for (int r = 0; r < 4; r++)
            #pragma unroll
            for (int nn = 0; nn < 8; nn++) {
                acc2[r][nn] = fmax2p(xv[r].x, wv[nn].x, acc2[r][nn]);
                acc2[r][nn] = fmax2p(xv[r].y, wv[nn].y, acc2[r][nn]);
            }
    }

    float bl[4], av[4];
    #pragma unroll
    for (int nn = 0; nn < 4; nn++) {
        bl[nn] = __ldg(b_lin + l + 32*nn);
        av[nn] = asA[l + 32*nn];
    }

    #pragma unroll
    for (int r = 0; r < 4; r++) {
        const int row = row0 + 4*w + r;
        float uval[4], vval[4];
        #pragma unroll
        for (int nn = 0; nn < 4; nn++) {
            uval[nn] = lo32(acc2[r][nn])   + hi32(acc2[r][nn]);
            vval[nn] = lo32(acc2[r][nn+4]) + hi32(acc2[r][nn+4]) + bl[nn];
            g_U [row*D_ + l + 32*nn] = uval[nn];
            g_Vb[row*D_ + l + 32*nn] = vval[nn];
        }
        float pa = 0.f, qa = 0.f;
        #pragma unroll
        for (int nn = 0; nn < 4; nn++) {
            pa = fmaf(av[nn], uval[nn], pa);
            qa = fmaf(av[nn], vval[nn], qa);
        }
        #pragma unroll
        for (int off = 16; off; off >>= 1) {
            pa += __shfl_down_sync(0xffffffffu, pa, off);
            qa += __shfl_down_sync(0xffffffffu, qa, off);
        }
        if (l == 0) { g_P[row] = pa; g_Q[row] = qa; }
    }
}

// ---------------------------------------------------------------------------
// Kernel B: transposed e-loop (32 warps), split epilogue.
// Grid (8 i-groups x 16 b) = 128 blocks, 1024 threads.
// e-loop: lane = i-row, warp w = j-chunk [8w, 8w+8).
// Epilogue: warp = (i-group w&7 -> 4 i's, j-chunk w>>3 -> 64 j's); smem reduce.
// ---------------------------------------------------------------------------
#define VBS_F   (K_*132)                   // 33792
#define US_OFF  (VBS_F)                    // + 32*132 = 4224
#define AS_OFF  (US_OFF + 32*132)          // 38016
#define QS_OFF  (AS_OFF + 128)             // 38144
#define PS_OFF  (QS_OFF + 256)             // 38400
#define MR_OFF  (PS_OFF + 32)              // 38432  (32*32)
#define SR_OFF  (MR_OFF + 1024)            // 39456  (32*32)
#define WS_OFF  (SR_OFF + 1024)            // 40480  (256*36)
#define KB_SMEM_FLOATS (WS_OFF + K_*36)    // 49696 floats = 198784 B
// overlays inside the dead Vbs region (post-softmax):
#define XO_F    0                          // x[b]: 16384 floats at sm+0
#define HR_OFF  16384                      // hred: 32i*4c*33 u64 = 8448 floats

__global__ void __launch_bounds__(1024)
kB(const float* __restrict__ x, const float* __restrict__ a,
   const float* __restrict__ bias, float* __restrict__ out)
{
    extern __shared__ float sm[];
    float* Vbs  = sm;
    float* Us   = sm + US_OFF;
    float* as_  = sm + AS_OFF;
    float* Qs   = sm + QS_OFF;
    float* Ps   = sm + PS_OFF;
    float* mred = sm + MR_OFF;
    float* sred = sm + SR_OFF;
    float* ws   = sm + WS_OFF;   // ws[j*36 + il]

    const int tid = threadIdx.x;
    const int b   = blockIdx.y;
    const int igbase = blockIdx.x * 32;

    // ---- stage Vb[b], 32 U rows, a, Q, P ----
    {
        const float4* vg4  = (const float4*)g_Vb + b * (K_*D_/4);
        float4*       vbs4 = (float4*)Vbs;
        for (int idx = tid; idx < K_*D_/4; idx += 1024) {
            const int j = idx >> 5, c = idx & 31;
            vbs4[j*33 + c] = vg4[idx];
        }
        const float4* ug4 = (const float4*)g_U + (b*K_ + igbase) * (D_/4);
        float4*       us4 = (float4*)Us;
        for (int idx = tid; idx < 32*D_/4; idx += 1024) {
            const int il = idx >> 5, c = idx & 31;
            us4[il*33 + c] = ug4[idx];
        }
        if (tid < 128) as_[tid] = a[tid];
        else if (tid >= 256 && tid < 512) Qs[tid - 256] = g_Q[b*K_ + tid - 256];
        else if (tid >= 512 && tid < 544) Ps[tid - 512] = g_P[b*K_ + igbase + tid - 512];
    }
    __syncthreads();

    const int w  = tid >> 5;
    const int l  = tid & 31;           // lane = local i row
    const int j0 = w * 8;              // warp's j chunk (8 rows)

    // ---- e-loop: acc[jj] = packed sum_d a_d * |u_{l,d} + vb_{j0+jj,d}| ----
    u64 acc[8];
    #pragma unroll
    for (int jj = 0; jj < 8; jj++) acc[jj] = 0ull;

    {
        const ulonglong2* vbs2 = (const ulonglong2*)Vbs;   // row stride 33
        const ulonglong2* us2  = (const ulonglong2*)Us;
        const ulonglong2* a2   = (const ulonglong2*)as_;
        for (int dc = 0; dc < 32; dc++) {
            const ulonglong2 uv = us2[l*33 + dc];          // lane-varying
            const ulonglong2 av = a2[dc];                  // broadcast
            ulonglong2 vv[8];
            #pragma unroll
            for (int jj = 0; jj < 8; jj++) vv[jj] = vbs2[(j0 + jj)*33 + dc];
            #pragma unroll
            for (int jj = 0; jj < 8; jj++) {
                u64 z;
                z = addx2(uv.x, vv[jj].x); acc[jj] = fmax2p(av.x, z & ABSMASK2, acc[jj]);
                z = addx2(uv.y, vv[jj].y); acc[jj] = fmax2p(av.y, z & ABSMASK2, acc[jj]);
            }
        }
    }

    // ---- finish e for (i=l, j=j0..j0+8), cross-warp softmax ----
    float e[8];
    {
        const float P  = Ps[l];
        const int   ig = igbase + l;
        const float4* brow4 = (const float4*)(bias + ig*K_ + j0);
        float m = -1e30f;
        #pragma unroll
        for (int q4 = 0; q4 < 2; q4++) {
            const float4 bv = brow4[q4];
            const float bb[4] = {bv.x, bv.y, bv.z, bv.w};
            #pragma unroll
            for (int r = 0; r < 4; r++) {
                const int jj = q4*4 + r;
                const float A  = lo32(acc[jj]) + hi32(acc[jj]);
                const float ev = fmaf(C_LIN, P + Qs[j0 + jj], fmaf(C_ABS, A, bb[r]));
                e[jj] = ev;
                m = fmaxf(m, ev);
            }
        }
        mred[w*32 + l] = m;
    }
    __syncthreads();
    {
        float M = mred[l];
        #pragma unroll
        for (int wp = 1; wp < 32; wp++) M = fmaxf(M, mred[wp*32 + l]);
        float s = 0.f;
        #pragma unroll
        for (int jj = 0; jj < 8; jj++) { e[jj] = __expf(e[jj] - M); s += e[jj]; }
        sred[w*32 + l] = s;
    }
    __syncthreads();
    {
        float S = sred[l];
        #pragma unroll
        for (int wp = 1; wp < 32; wp++) S += sred[wp*32 + l];
        const float inv = __fdividef(1.f, S);
        #pragma unroll
        for (int jj = 0; jj < 8; jj++)
            ws[(j0 + jj)*36 + l] = e[jj] * inv;
    }
    // overlay x[b] onto the dead Vbs region (same phase window)
    __syncthreads();
    {
        float4*       xs4 = (float4*)sm;
        const float4* xg4 = (const float4*)x + b * (K_*T_/4);
        for (int idx = tid; idx < K_*T_/4; idx += 1024) xs4[idx] = xg4[idx];
    }
    __syncthreads();

    // ---- epilogue stage 1: warp = (4 i's, 64 j's); partials -> hred ----
    u64* hred = (u64*)(sm + HR_OFF);   // hred[(i*4 + c)*33 + l]
    {
        const int g  = w & 7;          // i-group: i = 4g..4g+3
        const int c  = w >> 3;         // j-chunk: [64c, 64c+64)
        const u64* xs2 = (const u64*)sm;
        u64 h[4] = {0ull, 0ull, 0ull, 0ull};
        const int jbeg = 64*c;
        #pragma unroll 8
        for (int j = jbeg; j < jbeg + 64; j++) {
            const u64    xv = xs2[j*32 + l];
            const float4 wq = *(const float4*)(ws + j*36 + 4*g);   // broadcast
            h[0] = fmax2p(dup2(wq.x), xv, h[0]);
            h[1] = fmax2p(dup2(wq.y), xv, h[1]);
            h[2] = fmax2p(dup2(wq.z), xv, h[2]);
            h[3] = fmax2p(dup2(wq.w), xv, h[3]);
        }
        #pragma unroll
        for (int ii = 0; ii < 4; ii++)
            hred[((4*g + ii)*4 + c)*33 + l] = h[ii];
    }
    __syncthreads();

    // ---- epilogue stage 2: warp w -> i row w; combine 4 partials ----
    {
        u64 h = hred[(w*4 + 0)*33 + l];
        h = addx2(h, hred[(w*4 + 1)*33 + l]);
        h = addx2(h, hred[(w*4 + 2)*33 + l]);
        h = addx2(h, hred[(w*4 + 3)*33 + l]);
        const int row = (b*K_ + igbase + w)*T_ + 2*l;
        float2 o;
        o.x = __fdividef(1.f, 1.f + __expf(-lo32(h)));
        o.y = __fdividef(1.f, 1.f + __expf(-hi32(h)));
        *(float2*)(out + row) = o;
    }
}

// ---------------------------------------------------------------------------
extern "C" void kernel_launch(void* const* d_in, const int* in_sizes, int n_in,
                              void* d_out, int out_size)
{
    const float* x     = (const float*)d_in[0];
    // d_in[1] = embedding (unused by the reference computation)
    const float* W     = (const float*)d_in[2];
    const float* b_lin = (const float*)d_in[3];
    const float* a     = (const float*)d_in[4];
    const float* bias  = (const float*)d_in[5];
    float* out = (float*)d_out;

    const int smemA = KA_SMEM_FLOATS * 4;   // 78848 B
    const int smemB = KB_SMEM_FLOATS * 4;   // 198784 B
    cudaFuncSetAttribute(kA, cudaFuncAttributeMaxDynamicSharedMemorySize, smemA);
    cudaFuncSetAttribute(kB, cudaFuncAttributeMaxDynamicSharedMemorySize, smemB);

    kA<<<128, 256, smemA>>>(x, W, b_lin, a);
    kB<<<dim3(8, 16), 1024, smemB>>>(x, a, bias, out);
}